// round 15
// baseline (speedup 1.0000x reference)
#include <cuda_runtime.h>
#include <cstdint>
#include <cstddef>

#define B_     128
#define T_     32
#define NCAT   32
#define MAXCH  56
#define BM     128
#define BN     128
#define BK     32
#define NT     128

// SMEM (bytes): [0, 3*8704) B f16 tiles (16 kp x 136 w); then 3 A f16 stages
#define BSTR       136
#define BF16_BYTES (16 * BSTR * 4)               // 8704
#define A16_OFF    (3 * BF16_BYTES)              // 26112
#define A16_BYTES  (128 * 80)                    // 10240 (128 rows x 16 kp, pad 4)
#define SMEM_REQ   (A16_OFF + 3 * A16_BYTES)     // 56832

__device__ unsigned short g_x16[B_ * T_ * 1536];      // f16 input
__device__ unsigned short g_hidden16[B_ * T_ * 1024]; // f16 hidden

__device__ __forceinline__ uint32_t smem_u32(const void* p) {
    uint32_t a;
    asm("{ .reg .u64 t; cvta.to.shared.u64 t, %1; cvt.u32.u64 %0, t; }" : "=r"(a) : "l"(p));
    return a;
}
__device__ __forceinline__ void cpa16(uint32_t d, const void* s) {
    asm volatile("cp.async.cg.shared.global [%0], [%1], 16;" :: "r"(d), "l"(s));
}
// pack {lo=f16(lo), hi=f16(hi)} -- first PTX source is the HIGH half
__device__ __forceinline__ uint32_t packh2(float lo, float hi) {
    uint32_t r;
    asm("cvt.rn.f16x2.f32 %0, %1, %2;" : "=r"(r) : "f"(hi), "f"(lo));
    return r;
}

__global__ void cvt_x_kernel(const float4* __restrict__ x4) {
    int i = blockIdx.x * 256 + threadIdx.x;
    float4 v = x4[i];
    uint2 r;
    r.x = packh2(v.x, v.y);
    r.y = packh2(v.z, v.w);
    ((uint2*)g_x16)[i] = r;
}

// ---------------------------------------------------------------------------
// out[chunk 128 rows x 128 n] = act(A[128,K] @ W[cat][K,1024] + b)
// 128 threads = 4 warps (2x2) of 64x64 tiles -> crossbar-bytes/MMA halved.
// A: f16 cp.async NS=3. B: fp32 LDG -> f16 pack -> STS two chunks ahead, NS=3.
// One __syncthreads per iter; fragment double-buffering across ks. 2 CTAs/SM.
// ---------------------------------------------------------------------------
template <int K, bool RELU, bool IN_HID, bool OUT_HID>
__global__ __launch_bounds__(NT, 2)
void catmlp_gemm(const float* __restrict__ Wt, const float* __restrict__ bias,
                 const int* __restrict__ cat_ids, float* __restrict__ gout)
{
    extern __shared__ char smem[];
    const uint32_t sb = smem_u32(smem);

    __shared__ int cats[B_];
    __shared__ int s_cnt[NCAT], s_base[NCAT];
    __shared__ int s_cb[4], s_cat, s_nch;
    __shared__ const char* rowp[BM];

    const int tid  = threadIdx.x;
    const int wid  = tid >> 5;
    const int lane = tid & 31;
    const int bx   = blockIdx.x;

    // ---- per-CTA chunk decomposition (groups of <=4 same-cat batches) ----
    cats[tid] = cat_ids[tid];
    __syncthreads();
    if (wid == 0) {
        int n = 0;
        #pragma unroll 4
        for (int b = 0; b < B_; b++) n += (cats[b] == lane);
        int ch = (n + 3) >> 2;
        int inc = ch;
        #pragma unroll
        for (int d = 1; d < 32; d <<= 1) {
            int v = __shfl_up_sync(0xffffffffu, inc, d);
            if (lane >= d) inc += v;
        }
        s_cnt[lane]  = n;
        s_base[lane] = inc - ch;
        if (lane == 31) s_nch = inc;
        bool own = (bx >= inc - ch) && (bx < inc);
        uint32_t m = __ballot_sync(0xffffffffu, own);
        if (lane == 0) s_cat = m ? (__ffs(m) - 1) : 0;
    }
    __syncthreads();
    if (bx >= s_nch) return;

    const int cat = s_cat;
    const int jg  = bx - s_base[cat];
    const int ncc = s_cnt[cat];
    if (cats[tid] == cat) {
        int r = 0;
        for (int b = 0; b < tid; b++) r += (cats[b] == cat);
        int nv = ncc - jg * 4;
        if (nv > 4) nv = 4;
        if (r >= jg * 4 && r < jg * 4 + 4) s_cb[r - jg * 4] = tid;
        if (r == ncc - 1)
            for (int q = nv; q < 4; q++) s_cb[q] = tid;  // pad by replication
    }
    __syncthreads();

    const unsigned short* in16 = IN_HID ? g_hidden16 : g_x16;
    {
        int b = s_cb[tid >> 5];
        rowp[tid] = (const char*)(in16 + ((size_t)b * T_ + (tid & 31)) * (size_t)K);
    }
    const float* Wc = Wt + (size_t)cat * K * 1024;
    const int n0 = blockIdx.y * BN;
    __syncthreads();

    constexpr int NC = K / BK;

    auto stageA = [&](int ch) {
        const uint32_t ab = sb + A16_OFF + (ch % 3) * A16_BYTES;
        const int k2 = 2 * ch * BK;               // byte offset into f16 row
        #pragma unroll
        for (int j = 0; j < 4; j++) {             // 512 x 16B chunks / 128 thr
            int c   = tid + (j << 7);
            int row = c >> 2;
            int g   = c & 3;
            cpa16(ab + row * 80 + g * 16, rowp[row] + k2 + 16 * g);
        }
        asm volatile("cp.async.commit_group;" ::: "memory");
    };

    // full-chunk B convert (prologue only): LDG fp32 -> pack -> STS f16 tile
    auto convB = [&](int ch) {
        const int k0 = ch * BK;
        uint32_t* Bp = (uint32_t*)(smem + (ch % 3) * BF16_BYTES);
        #pragma unroll
        for (int j = 0; j < 4; j++) {
            int q  = tid + (j << 7);
            int kp = q >> 5, qn = q & 31;
            const float* s = Wc + (size_t)(k0 + 2 * kp) * 1024 + n0 + 4 * qn;
            float4 v0 = *(const float4*)s;
            float4 v1 = *(const float4*)(s + 1024);
            uint4 w;
            w.x = packh2(v0.x, v1.x); w.y = packh2(v0.y, v1.y);
            w.z = packh2(v0.z, v1.z); w.w = packh2(v0.w, v1.w);
            *(uint4*)(Bp + kp * BSTR + 4 * qn) = w;
        }
    };

    stageA(0);
    stageA(1);
    convB(0);
    convB(1);

    const int wm = (wid & 1) * 64;               // 0 / 64 (M warp)
    const int wn = (wid >> 1) * 64;              // 0 / 64 (N warp)
    const int lg = lane >> 2;
    const int lr = lane & 3;

    float acc[4][8][4];
    #pragma unroll
    for (int mf = 0; mf < 4; mf++)
        #pragma unroll
        for (int nf = 0; nf < 8; nf++)
            #pragma unroll
            for (int q = 0; q < 4; q++) acc[mf][nf][q] = 0.f;

    uint32_t ua[2][4][4];                        // [buf][mf][frag]
    uint32_t ub[2][8][2];                        // [buf][nf][frag]

    for (int i = 0; i < NC; i++) {
        if (i < NC - 1) asm volatile("cp.async.wait_group 1;" ::: "memory");
        else            asm volatile("cp.async.wait_group 0;" ::: "memory");
        __syncthreads();                          // ONE barrier per iteration

        const uint32_t* As16 = (const uint32_t*)(smem + A16_OFF + (size_t)(i % 3) * A16_BYTES);
        const uint32_t* Bp   = (const uint32_t*)(smem + (size_t)(i % 3) * BF16_BYTES);

        const bool pf = (i + 2 < NC);
        const int k2 = (i + 2) * BK;
        uint32_t* Bp2 = (uint32_t*)(smem + (size_t)((i + 2) % 3) * BF16_BYTES);
        float4 h[2][2];

        // fragment loader for k16 step ks into buffer b
        auto loadFrags = [&](int ks, int b) {
            const int c0 = (ks << 3) + lr;
            #pragma unroll
            for (int mf = 0; mf < 4; mf++) {
                const int r0 = wm + mf * 16 + lg;
                ua[b][mf][0] = As16[(r0    ) * 20 + c0];
                ua[b][mf][1] = As16[(r0 + 8) * 20 + c0];
                ua[b][mf][2] = As16[(r0    ) * 20 + c0 + 4];
                ua[b][mf][3] = As16[(r0 + 8) * 20 + c0 + 4];
            }
            const int nb = wn + lg;
            #pragma unroll
            for (int nf = 0; nf < 8; nf++) {
                ub[b][nf][0] = Bp[(c0    ) * BSTR + nb + nf * 8];
                ub[b][nf][1] = Bp[(c0 + 4) * BSTR + nb + nf * 8];
            }
        };
        auto mmaBurst = [&](int b) {
            #pragma unroll
            for (int mf = 0; mf < 4; mf++)
                #pragma unroll
                for (int nf = 0; nf < 8; nf++)
                    asm volatile(
                        "mma.sync.aligned.m16n8k16.row.col.f32.f16.f16.f32 "
                        "{%0,%1,%2,%3}, {%4,%5,%6,%7}, {%8,%9}, {%0,%1,%2,%3};"
                        : "+f"(acc[mf][nf][0]), "+f"(acc[mf][nf][1]),
                          "+f"(acc[mf][nf][2]), "+f"(acc[mf][nf][3])
                        : "r"(ua[b][mf][0]), "r"(ua[b][mf][1]),
                          "r"(ua[b][mf][2]), "r"(ua[b][mf][3]),
                          "r"(ub[b][nf][0]), "r"(ub[b][nf][1]));
        };

        loadFrags(0, 0);
        if (pf) {                                 // LDG wave 0 of B chunk i+2
            #pragma unroll
            for (int j = 0; j < 2; j++) {
                int q  = tid + (j << 7);
                int kp = q >> 5, qn = q & 31;
                const float* s = Wc + (size_t)(k2 + 2 * kp) * 1024 + n0 + 4 * qn;
                h[j][0] = *(const float4*)s;
                h[j][1] = *(const float4*)(s + 1024);
            }
        }
        loadFrags(1, 1);                          // dbuf: frags for ks=1 in flight
        mmaBurst(0);                              // 32 MMAs over buffer 0
        if (pf) {                                 // STS wave 0, LDG wave 1
            #pragma unroll
            for (int j = 0; j < 2; j++) {
                int q  = tid + (j << 7);
                int kp = q >> 5, qn = q & 31;
                uint4 w;
                w.x = packh2(h[j][0].x, h[j][1].x);
                w.y = packh2(h[j][0].y, h[j][1].y);
                w.z = packh2(h[j][0].z, h[j][1].z);
                w.w = packh2(h[j][0].w, h[j][1].w);
                *(uint4*)(Bp2 + kp * BSTR + 4 * qn) = w;
            }
            #pragma unroll
            for (int j = 0; j < 2; j++) {
                int q  = tid + ((j + 2) << 7);
                int kp = q >> 5, qn = q & 31;
                const float* s = Wc + (size_t)(k2 + 2 * kp) * 1024 + n0 + 4 * qn;
                h[j][0] = *(const float4*)s;
                h[j][1] = *(const float4*)(s + 1024);
            }
        }
        mmaBurst(1);                              // 32 MMAs over buffer 1
        if (pf) {                                 // STS wave 1 + A refill
            #pragma unroll
            for (int j = 0; j < 2; j++) {
                int q  = tid + ((j + 2) << 7);
                int kp = q >> 5, qn = q & 31;
                uint4 w;
                w.x = packh2(h[j][0].x, h[j][1].x);
                w.y = packh2(h[j][0].y, h[j][1].y);
                w.z = packh2(h[j][0].z, h[j][1].z);
                w.w = packh2(h[j][0].w, h[j][1].w);
                *(uint4*)(Bp2 + kp * BSTR + 4 * qn) = w;
            }
            stageA(i + 2);
        }
    }

    // ---- epilogue ----
    const float* brow = bias + (size_t)cat * 1024 + n0;
    float2 bb[8];
    #pragma unroll
    for (int nf = 0; nf < 8; nf++)
        bb[nf] = *(const float2*)(brow + wn + nf * 8 + lr * 2);

    #pragma unroll
    for (int mf = 0; mf < 4; mf++) {
        const int r0 = wm + mf * 16 + lg;         // 0..127; r0, r0+8 same 32-slab
        const int batch = s_cb[r0 >> 5];
        #pragma unroll
        for (int nf = 0; nf < 8; nf++) {
            const int col = wn + nf * 8 + lr * 2;
            float v0x = acc[mf][nf][0] + bb[nf].x;
            float v0y = acc[mf][nf][1] + bb[nf].y;
            float v1x = acc[mf][nf][2] + bb[nf].x;
            float v1y = acc[mf][nf][3] + bb[nf].y;
            if (RELU) {
                v0x = fmaxf(v0x, 0.f); v0y = fmaxf(v0y, 0.f);
                v1x = fmaxf(v1x, 0.f); v1y = fmaxf(v1y, 0.f);
            }
            if (OUT_HID) {                        // packed f16 hidden store
                uint32_t* o16 = (uint32_t*)g_hidden16;
                size_t w0 = (((size_t)batch * T_ + (r0 & 31)      ) * 1024 + n0 + col) >> 1;
                size_t w1 = (((size_t)batch * T_ + ((r0 + 8) & 31)) * 1024 + n0 + col) >> 1;
                o16[w0] = packh2(v0x, v0y);
                o16[w1] = packh2(v1x, v1y);
            } else {
                float* o0 = gout + ((size_t)batch * T_ + (r0 & 31)      ) * 1024 + n0 + col;
                float* o1 = gout + ((size_t)batch * T_ + ((r0 + 8) & 31)) * 1024 + n0 + col;
                *(float2*)o0 = make_float2(v0x, v0y);
                *(float2*)o1 = make_float2(v1x, v1y);
            }
        }
    }
}

// ---------------------------------------------------------------------------
extern "C" void kernel_launch(void* const* d_in, const int* in_sizes, int n_in,
                              void* d_out, int out_size) {
    const float* x   = (const float*)d_in[0];
    const int*   cat = (const int*)  d_in[1];
    const float* W1  = (const float*)d_in[2];
    const float* b1  = (const float*)d_in[3];
    const float* W2  = (const float*)d_in[4];
    const float* b2  = (const float*)d_in[5];
    float*       out = (float*)d_out;

    cudaFuncSetAttribute(catmlp_gemm<1536, true,  false, true >,
                         cudaFuncAttributeMaxDynamicSharedMemorySize, SMEM_REQ);
    cudaFuncSetAttribute(catmlp_gemm<1024, false, true,  false>,
                         cudaFuncAttributeMaxDynamicSharedMemorySize, SMEM_REQ);

    cvt_x_kernel<<<(B_ * T_ * 1536) / (256 * 4), 256>>>((const float4*)x);

    dim3 grid(MAXCH, 1024 / BN);
    catmlp_gemm<1536, true,  false, true ><<<grid, NT, SMEM_REQ>>>(W1, b1, cat, nullptr);
    catmlp_gemm<1024, false, true,  false><<<grid, NT, SMEM_REQ>>>(W2, b2, cat, out);
}

// round 16
// speedup vs baseline: 1.0740x; 1.0740x over previous
#include <cuda_runtime.h>
#include <cstdint>
#include <cstddef>

#define B_     128
#define T_     32
#define NCAT   32
#define MAXCH  80
#define BM     64
#define BN     128
#define BK     32
#define NT     256

// SMEM (bytes): [0, 3*8704) B f16 tiles (16 kp x 136 w); then 3 A f16 stages
#define BSTR       136
#define BF16_BYTES (16 * BSTR * 4)               // 8704
#define A16_OFF    (3 * BF16_BYTES)              // 26112
#define A16_BYTES  (64 * 80)                     // 5120 (64 rows x 16 kp, pad 4w)
#define SMEM_REQ   (A16_OFF + 3 * A16_BYTES)     // 41472

__device__ unsigned short g_x16[B_ * T_ * 1536];      // f16 input
__device__ unsigned short g_hidden16[B_ * T_ * 1024]; // f16 hidden

__device__ __forceinline__ uint32_t smem_u32(const void* p) {
    uint32_t a;
    asm("{ .reg .u64 t; cvta.to.shared.u64 t, %1; cvt.u32.u64 %0, t; }" : "=r"(a) : "l"(p));
    return a;
}
__device__ __forceinline__ void cpa16(uint32_t d, const void* s) {
    asm volatile("cp.async.cg.shared.global [%0], [%1], 16;" :: "r"(d), "l"(s));
}
// pack {lo=f16(lo), hi=f16(hi)} -- first PTX source is the HIGH half
__device__ __forceinline__ uint32_t packh2(float lo, float hi) {
    uint32_t r;
    asm("cvt.rn.f16x2.f32 %0, %1, %2;" : "=r"(r) : "f"(hi), "f"(lo));
    return r;
}

__global__ void cvt_x_kernel(const float4* __restrict__ x4) {
    int i = blockIdx.x * 256 + threadIdx.x;
    float4 v = x4[i];
    uint2 r;
    r.x = packh2(v.x, v.y);
    r.y = packh2(v.z, v.w);
    ((uint2*)g_x16)[i] = r;
}

// ---------------------------------------------------------------------------
// out[chunk 64 rows x 128 n] = act(A[64,K] @ W[cat][K,1024] + b)
// 256 threads = 8 warps (2M x 4N) of 32x32 tiles (acc 32 regs -> ~80 regs tot)
// => 3 CTAs/SM = 24 warps/SM, 6/SMSP: concurrency-driven latency hiding.
// A: f16 cp.async NS=3. B: fp32 LDG -> f16 pack -> STS two chunks ahead, NS=3.
// One __syncthreads per iteration.
// ---------------------------------------------------------------------------
template <int K, bool RELU, bool IN_HID, bool OUT_HID>
__global__ __launch_bounds__(NT, 3)
void catmlp_gemm(const float* __restrict__ Wt, const float* __restrict__ bias,
                 const int* __restrict__ cat_ids, float* __restrict__ gout)
{
    extern __shared__ char smem[];
    const uint32_t sb = smem_u32(smem);

    __shared__ int cats[B_];
    __shared__ int s_cnt[NCAT], s_base[NCAT];
    __shared__ int s_cb[2], s_cat, s_nch;
    __shared__ const char* rowp[BM];

    const int tid  = threadIdx.x;
    const int wid  = tid >> 5;
    const int lane = tid & 31;
    const int bx   = blockIdx.x;

    // ---- per-CTA chunk decomposition (groups of <=2 same-cat batches) ----
    if (tid < B_) cats[tid] = cat_ids[tid];
    __syncthreads();
    if (wid == 0) {
        int n = 0;
        #pragma unroll 4
        for (int b = 0; b < B_; b++) n += (cats[b] == lane);
        int ch = (n + 1) >> 1;
        int inc = ch;
        #pragma unroll
        for (int d = 1; d < 32; d <<= 1) {
            int v = __shfl_up_sync(0xffffffffu, inc, d);
            if (lane >= d) inc += v;
        }
        s_cnt[lane]  = n;
        s_base[lane] = inc - ch;
        if (lane == 31) s_nch = inc;
        bool own = (bx >= inc - ch) && (bx < inc);
        uint32_t m = __ballot_sync(0xffffffffu, own);
        if (lane == 0) s_cat = m ? (__ffs(m) - 1) : 0;
    }
    __syncthreads();
    if (bx >= s_nch) return;

    const int cat = s_cat;
    const int jg  = bx - s_base[cat];
    const int ncc = s_cnt[cat];
    if (tid < B_ && cats[tid] == cat) {
        int r = 0;
        for (int b = 0; b < tid; b++) r += (cats[b] == cat);
        int nv = ncc - jg * 2;
        if (nv > 2) nv = 2;
        if (r >= jg * 2 && r < jg * 2 + 2) s_cb[r - jg * 2] = tid;
        if (r == ncc - 1)
            for (int q = nv; q < 2; q++) s_cb[q] = tid;  // pad by replication
    }
    __syncthreads();

    const unsigned short* in16 = IN_HID ? g_hidden16 : g_x16;
    if (tid < BM) {
        int b = s_cb[tid >> 5];
        rowp[tid] = (const char*)(in16 + ((size_t)b * T_ + (tid & 31)) * (size_t)K);
    }
    const float* Wc = Wt + (size_t)cat * K * 1024;
    const int n0 = blockIdx.y * BN;
    __syncthreads();

    constexpr int NC = K / BK;

    auto stageA = [&](int ch) {
        const uint32_t ab = sb + A16_OFF + (ch % 3) * A16_BYTES;
        const int k2 = 2 * ch * BK;               // byte offset into f16 row
        {                                         // 256 x 16B chunks / 256 thr
            int row = tid >> 2;
            int g   = tid & 3;
            cpa16(ab + row * 80 + g * 16, rowp[row] + k2 + 16 * g);
        }
        asm volatile("cp.async.commit_group;" ::: "memory");
    };

    // full-chunk B convert (prologue only): LDG fp32 -> pack -> STS f16 tile
    auto convB = [&](int ch) {
        const int k0 = ch * BK;
        uint32_t* Bp = (uint32_t*)(smem + (ch % 3) * BF16_BYTES);
        #pragma unroll
        for (int j = 0; j < 2; j++) {
            int q  = tid + (j << 8);
            int kp = q >> 5, qn = q & 31;
            const float* s = Wc + (size_t)(k0 + 2 * kp) * 1024 + n0 + 4 * qn;
            float4 v0 = *(const float4*)s;
            float4 v1 = *(const float4*)(s + 1024);
            uint4 w;
            w.x = packh2(v0.x, v1.x); w.y = packh2(v0.y, v1.y);
            w.z = packh2(v0.z, v1.z); w.w = packh2(v0.w, v1.w);
            *(uint4*)(Bp + kp * BSTR + 4 * qn) = w;
        }
    };

    stageA(0);
    stageA(1);
    convB(0);
    convB(1);

    const int wm = (wid & 1) * 32;               // 0 / 32       (M warp)
    const int wn = (wid >> 1) * 32;              // 0/32/64/96   (N warp)
    const int lg = lane >> 2;
    const int lr = lane & 3;

    float acc[2][4][4];
    #pragma unroll
    for (int mf = 0; mf < 2; mf++)
        #pragma unroll
        for (int nf = 0; nf < 4; nf++)
            #pragma unroll
            for (int q = 0; q < 4; q++) acc[mf][nf][q] = 0.f;

    for (int i = 0; i < NC; i++) {
        if (i < NC - 1) asm volatile("cp.async.wait_group 1;" ::: "memory");
        else            asm volatile("cp.async.wait_group 0;" ::: "memory");
        __syncthreads();                          // ONE barrier per iteration

        const uint32_t* As16 = (const uint32_t*)(smem + A16_OFF + (size_t)(i % 3) * A16_BYTES);
        const uint32_t* Bp   = (const uint32_t*)(smem + (size_t)(i % 3) * BF16_BYTES);

        const bool pf = (i + 2 < NC);
        const int k2 = (i + 2) * BK;
        uint32_t* Bp2 = (uint32_t*)(smem + (size_t)((i + 2) % 3) * BF16_BYTES);
        float4 h0, h1;

        // -- LDG wave 0 of B chunk i+2 --
        if (pf) {
            int kp = tid >> 5, qn = tid & 31;
            const float* s = Wc + (size_t)(k2 + 2 * kp) * 1024 + n0 + 4 * qn;
            h0 = *(const float4*)s;
            h1 = *(const float4*)(s + 1024);
        }

        #pragma unroll
        for (int ks = 0; ks < 2; ks++) {
            const int c0 = (ks << 3) + lr;        // kpair col
            uint32_t ua[2][4];
            #pragma unroll
            for (int mf = 0; mf < 2; mf++) {
                const int r0 = wm + mf * 16 + lg;
                ua[mf][0] = As16[(r0    ) * 20 + c0];
                ua[mf][1] = As16[(r0 + 8) * 20 + c0];
                ua[mf][2] = As16[(r0    ) * 20 + c0 + 4];
                ua[mf][3] = As16[(r0 + 8) * 20 + c0 + 4];
            }
            uint32_t ub[4][2];
            const int nb = wn + lg;
            #pragma unroll
            for (int nf = 0; nf < 4; nf++) {
                ub[nf][0] = Bp[(c0    ) * BSTR + nb + nf * 8];
                ub[nf][1] = Bp[(c0 + 4) * BSTR + nb + nf * 8];
            }
            #pragma unroll
            for (int mf = 0; mf < 2; mf++)
                #pragma unroll
                for (int nf = 0; nf < 4; nf++)
                    asm volatile(
                        "mma.sync.aligned.m16n8k16.row.col.f32.f16.f16.f32 "
                        "{%0,%1,%2,%3}, {%4,%5,%6,%7}, {%8,%9}, {%0,%1,%2,%3};"
                        : "+f"(acc[mf][nf][0]), "+f"(acc[mf][nf][1]),
                          "+f"(acc[mf][nf][2]), "+f"(acc[mf][nf][3])
                        : "r"(ua[mf][0]), "r"(ua[mf][1]), "r"(ua[mf][2]), "r"(ua[mf][3]),
                          "r"(ub[nf][0]), "r"(ub[nf][1]));

            // between ks steps: drain wave 0, launch wave 1 (chunk i+2)
            if (ks == 0 && pf) {
                int kp = tid >> 5, qn = tid & 31;
                uint4 w;
                w.x = packh2(h0.x, h1.x); w.y = packh2(h0.y, h1.y);
                w.z = packh2(h0.z, h1.z); w.w = packh2(h0.w, h1.w);
                *(uint4*)(Bp2 + kp * BSTR + 4 * qn) = w;
                int q2 = tid + 256;
                kp = q2 >> 5; qn = q2 & 31;
                const float* s = Wc + (size_t)(k2 + 2 * kp) * 1024 + n0 + 4 * qn;
                h0 = *(const float4*)s;
                h1 = *(const float4*)(s + 1024);
            }
        }

        // -- drain wave 1 of B chunk i+2; refill A --
        if (pf) {
            int q2 = tid + 256;
            int kp = q2 >> 5, qn = q2 & 31;
            uint4 w;
            w.x = packh2(h0.x, h1.x); w.y = packh2(h0.y, h1.y);
            w.z = packh2(h0.z, h1.z); w.w = packh2(h0.w, h1.w);
            *(uint4*)(Bp2 + kp * BSTR + 4 * qn) = w;
            stageA(i + 2);
        }
    }

    // ---- epilogue ----
    const float* brow = bias + (size_t)cat * 1024 + n0;
    float2 bb[4];
    #pragma unroll
    for (int nf = 0; nf < 4; nf++)
        bb[nf] = *(const float2*)(brow + wn + nf * 8 + lr * 2);

    #pragma unroll
    for (int mf = 0; mf < 2; mf++) {
        const int r0 = wm + mf * 16 + lg;         // 0..63
        const int batch = s_cb[r0 >> 5];
        #pragma unroll
        for (int nf = 0; nf < 4; nf++) {
            const int col = wn + nf * 8 + lr * 2;
            float v0x = acc[mf][nf][0] + bb[nf].x;
            float v0y = acc[mf][nf][1] + bb[nf].y;
            float v1x = acc[mf][nf][2] + bb[nf].x;
            float v1y = acc[mf][nf][3] + bb[nf].y;
            if (RELU) {
                v0x = fmaxf(v0x, 0.f); v0y = fmaxf(v0y, 0.f);
                v1x = fmaxf(v1x, 0.f); v1y = fmaxf(v1y, 0.f);
            }
            if (OUT_HID) {                        // packed f16 hidden store
                uint32_t* o16 = (uint32_t*)g_hidden16;
                size_t w0 = (((size_t)batch * T_ + (r0 & 31)      ) * 1024 + n0 + col) >> 1;
                size_t w1 = (((size_t)batch * T_ + ((r0 + 8) & 31)) * 1024 + n0 + col) >> 1;
                o16[w0] = packh2(v0x, v0y);
                o16[w1] = packh2(v1x, v1y);
            } else {
                float* o0 = gout + ((size_t)batch * T_ + (r0 & 31)      ) * 1024 + n0 + col;
                float* o1 = gout + ((size_t)batch * T_ + ((r0 + 8) & 31)) * 1024 + n0 + col;
                *(float2*)o0 = make_float2(v0x, v0y);
                *(float2*)o1 = make_float2(v1x, v1y);
            }
        }
    }
}

// ---------------------------------------------------------------------------
extern "C" void kernel_launch(void* const* d_in, const int* in_sizes, int n_in,
                              void* d_out, int out_size) {
    const float* x   = (const float*)d_in[0];
    const int*   cat = (const int*)  d_in[1];
    const float* W1  = (const float*)d_in[2];
    const float* b1  = (const float*)d_in[3];
    const float* W2  = (const float*)d_in[4];
    const float* b2  = (const float*)d_in[5];
    float*       out = (float*)d_out;

    cudaFuncSetAttribute(catmlp_gemm<1536, true,  false, true >,
                         cudaFuncAttributeMaxDynamicSharedMemorySize, SMEM_REQ);
    cudaFuncSetAttribute(catmlp_gemm<1024, false, true,  false>,
                         cudaFuncAttributeMaxDynamicSharedMemorySize, SMEM_REQ);

    cvt_x_kernel<<<(B_ * T_ * 1536) / (256 * 4), 256>>>((const float4*)x);

    dim3 grid(MAXCH, 1024 / BN);
    catmlp_gemm<1536, true,  false, true ><<<grid, NT, SMEM_REQ>>>(W1, b1, cat, nullptr);
    catmlp_gemm<1024, false, true,  false><<<grid, NT, SMEM_REQ>>>(W2, b2, cat, out);
}